// round 5
// baseline (speedup 1.0000x reference)
#include <cuda_runtime.h>

#define N_MAX 50000
#define E_MAX 800000
#define IN_FEATS 128
#define HF 64

// Scratch (device globals; no allocation allowed)
__device__ int   g_cnt[N_MAX];
__device__ int   g_off[N_MAX + 1];
__device__ int   g_cur[N_MAX];
__device__ int   g_bsum[256];
__device__ int   g_esrc[E_MAX];
__device__ float g_dinv[N_MAX];
__device__ float g_x[N_MAX * HF];
__device__ float g_f1[N_MAX * HF];
__device__ float g_f2[N_MAX * HF];
__device__ float g_M[HF * 192];

// ---------------------------------------------------------------------------
__global__ void zero_cnt_kernel(int n) {
    int i = blockIdx.x * blockDim.x + threadIdx.x;
    if (i < n) g_cnt[i] = 0;
}

__global__ void count_kernel(const int* __restrict__ dst, int e) {
    int i = blockIdx.x * blockDim.x + threadIdx.x;
    if (i < e) atomicAdd(&g_cnt[dst[i]], 1);
}

// ---- prefix scan over g_cnt -> g_off (exclusive) ----------------------------
__global__ void scan1_kernel(int n) {
    __shared__ int sh[256];
    int t = threadIdx.x;
    int i = blockIdx.x * 256 + t;
    int v = (i < n) ? g_cnt[i] : 0;
    sh[t] = v;
    __syncthreads();
#pragma unroll
    for (int o = 1; o < 256; o <<= 1) {
        int add = (t >= o) ? sh[t - o] : 0;
        __syncthreads();
        sh[t] += add;
        __syncthreads();
    }
    if (i < n) g_off[i] = sh[t] - v;
    if (t == 255) g_bsum[blockIdx.x] = sh[255];
}

__global__ void scan2_kernel(int nb) {
    __shared__ int sh[256];
    int t = threadIdx.x;
    int v = (t < nb) ? g_bsum[t] : 0;
    sh[t] = v;
    __syncthreads();
#pragma unroll
    for (int o = 1; o < 256; o <<= 1) {
        int add = (t >= o) ? sh[t - o] : 0;
        __syncthreads();
        sh[t] += add;
        __syncthreads();
    }
    if (t < nb) g_bsum[t] = sh[t] - v;
}

// scan3 + dinv fused
__global__ void scan3_kernel(int n, int e) {
    int i = blockIdx.x * blockDim.x + threadIdx.x;
    if (i < n) {
        int o = g_off[i] + g_bsum[i >> 8];
        g_off[i] = o;
        g_cur[i] = o;
        g_dinv[i] = rsqrtf(fmaxf((float)g_cnt[i], 1.0f));
    }
    if (i == 0) g_off[n] = e;
}

__global__ void fill_kernel(const int* __restrict__ src,
                            const int* __restrict__ dst, int e) {
    int i = blockIdx.x * blockDim.x + threadIdx.x;
    if (i < e) {
        int d = dst[i];
        int pos = atomicAdd(&g_cur[d], 1);
        g_esrc[pos] = src[i];
    }
}

// ---------------------------------------------------------------------------
// Gather SpMM with 2-deep index prefetch + unroll-by-2.
// fout[d] = fin[d] - dinv[d] * sum_{s in N(d)} dinv[s]*fin[s]
// step 0: g_x -> g_f1;  step 1: g_f1 -> g_f2.
__global__ __launch_bounds__(256) void spmm_kernel(int n, int step) {
    const float* fin = (step == 0) ? g_x : g_f1;
    float* fout      = (step == 0) ? g_f1 : g_f2;
    int w = (blockIdx.x * blockDim.x + threadIdx.x) >> 5;
    int lane = threadIdx.x & 31;
    if (w >= n) return;
    int beg = g_off[w];
    int end = g_off[w + 1];
    const float2* F = reinterpret_cast<const float2*>(fin);
    float2 acc = make_float2(0.f, 0.f);

    int j = beg;
    int sA = 0, sB = 0;
    if (j < end)     sA = __ldg(&g_esrc[j]);
    if (j + 1 < end) sB = __ldg(&g_esrc[j + 1]);
    while (j + 2 <= end) {
        float wA = __ldg(&g_dinv[sA]);
        float2 vA = F[sA * 32 + lane];
        float wB = __ldg(&g_dinv[sB]);
        float2 vB = F[sB * 32 + lane];
        int jn = j + 2;
        if (jn < end)     sA = __ldg(&g_esrc[jn]);
        if (jn + 1 < end) sB = __ldg(&g_esrc[jn + 1]);
        acc.x = fmaf(wA, vA.x, acc.x);
        acc.y = fmaf(wA, vA.y, acc.y);
        acc.x = fmaf(wB, vB.x, acc.x);
        acc.y = fmaf(wB, vB.y, acc.y);
        j = jn;
    }
    if (j < end) {  // at most one tail edge; its index is in sA
        float wt = __ldg(&g_dinv[sA]);
        float2 v = F[sA * 32 + lane];
        acc.x = fmaf(wt, v.x, acc.x);
        acc.y = fmaf(wt, v.y, acc.y);
    }

    float wd = g_dinv[w];
    float2 xv = F[w * 32 + lane];
    float2 r = make_float2(xv.x - wd * acc.x, xv.y - wd * acc.y);
    reinterpret_cast<float2*>(fout)[w * 32 + lane] = r;
}

// ---------------------------------------------------------------------------
// GEMM1: g_x = relu(features[n,128] @ W1[64,128]^T + b1)
// 256 threads, M-tile 256, N=64. Each thread: 8 rows x 8 cols, scalar FFMA.
__global__ __launch_bounds__(256) void gemm1_kernel(
    const float* __restrict__ A, const float* __restrict__ W1,
    const float* __restrict__ b1, int n) {
    __shared__ float As[32][260];
    __shared__ float Bs[32][68];
    int t = threadIdx.x;
    int m0 = blockIdx.x * 256;
    int tx = t & 7, ty = t >> 3;       // tx: 8 col-groups, ty: 32 row-groups
    int kv = t & 7, mrow = t >> 3;     // A-load mapping

    float acc[8][8];
#pragma unroll
    for (int i = 0; i < 8; i++)
#pragma unroll
        for (int j = 0; j < 8; j++) acc[i][j] = 0.f;

    for (int k0 = 0; k0 < IN_FEATS; k0 += 32) {
        // A: 256 rows x 32 k = 8 float4 per thread
#pragma unroll
        for (int i = 0; i < 8; i++) {
            int m = i * 32 + mrow;
            int gm = m0 + m;
            float4 v = make_float4(0.f, 0.f, 0.f, 0.f);
            if (gm < n)
                v = *reinterpret_cast<const float4*>(A + (size_t)gm * IN_FEATS + k0 + kv * 4);
            As[kv * 4 + 0][m] = v.x;
            As[kv * 4 + 1][m] = v.y;
            As[kv * 4 + 2][m] = v.z;
            As[kv * 4 + 3][m] = v.w;
        }
        // B: 64 rows x 32 k = 2 float4 per thread
#pragma unroll
        for (int i = 0; i < 2; i++) {
            int fl = t * 2 + i;
            int nn = fl >> 3, kv2 = fl & 7;
            float4 v = *reinterpret_cast<const float4*>(W1 + (size_t)nn * IN_FEATS + k0 + kv2 * 4);
            Bs[kv2 * 4 + 0][nn] = v.x;
            Bs[kv2 * 4 + 1][nn] = v.y;
            Bs[kv2 * 4 + 2][nn] = v.z;
            Bs[kv2 * 4 + 3][nn] = v.w;
        }
        __syncthreads();
#pragma unroll
        for (int k = 0; k < 32; k++) {
            float a[8], b[8];
            float4 aA = *reinterpret_cast<float4*>(&As[k][ty * 8]);
            float4 aB = *reinterpret_cast<float4*>(&As[k][ty * 8 + 4]);
            float4 bA = *reinterpret_cast<float4*>(&Bs[k][tx * 8]);
            float4 bB = *reinterpret_cast<float4*>(&Bs[k][tx * 8 + 4]);
            a[0] = aA.x; a[1] = aA.y; a[2] = aA.z; a[3] = aA.w;
            a[4] = aB.x; a[5] = aB.y; a[6] = aB.z; a[7] = aB.w;
            b[0] = bA.x; b[1] = bA.y; b[2] = bA.z; b[3] = bA.w;
            b[4] = bB.x; b[5] = bB.y; b[6] = bB.z; b[7] = bB.w;
#pragma unroll
            for (int i = 0; i < 8; i++)
#pragma unroll
                for (int j = 0; j < 8; j++)
                    acc[i][j] = fmaf(a[i], b[j], acc[i][j]);
        }
        __syncthreads();
    }
#pragma unroll
    for (int i = 0; i < 8; i++) {
        int gm = m0 + ty * 8 + i;
        if (gm < n) {
            float o[8];
#pragma unroll
            for (int j = 0; j < 8; j++) {
                float v = acc[i][j] + b1[tx * 8 + j];
                o[j] = v > 0.f ? v : 0.f;
            }
            float4* dst = reinterpret_cast<float4*>(&g_x[(size_t)gm * HF + tx * 8]);
            dst[0] = make_float4(o[0], o[1], o[2], o[3]);
            dst[1] = make_float4(o[4], o[5], o[6], o[7]);
        }
    }
}

// ---------------------------------------------------------------------------
// Fold thetas into W2: M[r][p*64+c] = sum_j THETA[j][p] * W2[r][j*64+c]
__global__ void buildM_kernel(const float* __restrict__ W2) {
    int t = blockIdx.x * blockDim.x + threadIdx.x;
    if (t >= HF * 192) return;
    int r = t / 192, k = t % 192;
    int p = k >> 6, c = k & 63;
    const float cA[3] = {3.0f, -3.0f, 0.75f};
    const float cB[3] = {0.0f, 3.0f, -1.5f};
    const float cC[3] = {0.0f, 0.0f, 0.75f};
    g_M[t] = cA[p] * W2[r * 192 + c]
           + cB[p] * W2[r * 192 + 64 + c]
           + cC[p] * W2[r * 192 + 128 + c];
}

// GEMM2: out = [x | f1 | f2] @ M^T + b2   (K=192), same 8x8 scalar scheme
__global__ __launch_bounds__(256) void gemm2_kernel(
    const float* __restrict__ b2, float* __restrict__ out, int n) {
    __shared__ float As[32][260];
    __shared__ float Bs[32][68];
    int t = threadIdx.x;
    int m0 = blockIdx.x * 256;
    int tx = t & 7, ty = t >> 3;
    int kv = t & 7, mrow = t >> 3;

    float acc[8][8];
#pragma unroll
    for (int i = 0; i < 8; i++)
#pragma unroll
        for (int j = 0; j < 8; j++) acc[i][j] = 0.f;

#pragma unroll
    for (int cch = 0; cch < 6; cch++) {
        const float* S = (cch < 2) ? g_x : (cch < 4) ? g_f1 : g_f2;
        int koff = (cch & 1) * 32;
#pragma unroll
        for (int i = 0; i < 8; i++) {
            int m = i * 32 + mrow;
            int gm = m0 + m;
            float4 v = make_float4(0.f, 0.f, 0.f, 0.f);
            if (gm < n)
                v = *reinterpret_cast<const float4*>(S + (size_t)gm * HF + koff + kv * 4);
            As[kv * 4 + 0][m] = v.x;
            As[kv * 4 + 1][m] = v.y;
            As[kv * 4 + 2][m] = v.z;
            As[kv * 4 + 3][m] = v.w;
        }
#pragma unroll
        for (int i = 0; i < 2; i++) {
            int fl = t * 2 + i;
            int nn = fl >> 3, kv2 = fl & 7;
            float4 v = *reinterpret_cast<const float4*>(g_M + (size_t)nn * 192 + cch * 32 + kv2 * 4);
            Bs[kv2 * 4 + 0][nn] = v.x;
            Bs[kv2 * 4 + 1][nn] = v.y;
            Bs[kv2 * 4 + 2][nn] = v.z;
            Bs[kv2 * 4 + 3][nn] = v.w;
        }
        __syncthreads();
#pragma unroll
        for (int k = 0; k < 32; k++) {
            float a[8], b[8];
            float4 aA = *reinterpret_cast<float4*>(&As[k][ty * 8]);
            float4 aB = *reinterpret_cast<float4*>(&As[k][ty * 8 + 4]);
            float4 bA = *reinterpret_cast<float4*>(&Bs[k][tx * 8]);
            float4 bB = *reinterpret_cast<float4*>(&Bs[k][tx * 8 + 4]);
            a[0] = aA.x; a[1] = aA.y; a[2] = aA.z; a[3] = aA.w;
            a[4] = aB.x; a[5] = aB.y; a[6] = aB.z; a[7] = aB.w;
            b[0] = bA.x; b[1] = bA.y; b[2] = bA.z; b[3] = bA.w;
            b[4] = bB.x; b[5] = bB.y; b[6] = bB.z; b[7] = bB.w;
#pragma unroll
            for (int i = 0; i < 8; i++)
#pragma unroll
                for (int j = 0; j < 8; j++)
                    acc[i][j] = fmaf(a[i], b[j], acc[i][j]);
        }
        __syncthreads();
    }
#pragma unroll
    for (int i = 0; i < 8; i++) {
        int gm = m0 + ty * 8 + i;
        if (gm < n) {
            float o[8];
#pragma unroll
            for (int j = 0; j < 8; j++) o[j] = acc[i][j] + b2[tx * 8 + j];
            float4* dst = reinterpret_cast<float4*>(&out[(size_t)gm * HF + tx * 8]);
            dst[0] = make_float4(o[0], o[1], o[2], o[3]);
            dst[1] = make_float4(o[4], o[5], o[6], o[7]);
        }
    }
}

// ---------------------------------------------------------------------------
extern "C" void kernel_launch(void* const* d_in, const int* in_sizes, int n_in,
                              void* d_out, int out_size) {
    const float* features = (const float*)d_in[0];
    const int*   src      = (const int*)d_in[1];
    const int*   dst      = (const int*)d_in[2];
    const float* W1       = (const float*)d_in[3];
    const float* b1       = (const float*)d_in[4];
    const float* W2       = (const float*)d_in[5];
    const float* b2       = (const float*)d_in[6];
    float* out = (float*)d_out;

    int n = in_sizes[0] / IN_FEATS;   // 50000
    int e = in_sizes[1];              // 800000
    int nb = (n + 255) / 256;         // 196

    // Fork a side stream for the CSR build; it is independent of GEMM1/buildM.
    cudaStream_t sA;
    cudaStreamCreateWithFlags(&sA, cudaStreamNonBlocking);
    cudaEvent_t e0, eA;
    cudaEventCreateWithFlags(&e0, cudaEventDisableTiming);
    cudaEventCreateWithFlags(&eA, cudaEventDisableTiming);

    cudaEventRecord(e0, 0);           // fork from capture (default) stream
    cudaStreamWaitEvent(sA, e0, 0);

    // CSR build chain on side stream
    zero_cnt_kernel<<<nb, 256, 0, sA>>>(n);
    count_kernel<<<(e + 255) / 256, 256, 0, sA>>>(dst, e);
    scan1_kernel<<<nb, 256, 0, sA>>>(n);
    scan2_kernel<<<1, 256, 0, sA>>>(nb);
    scan3_kernel<<<nb, 256, 0, sA>>>(n, e);
    fill_kernel<<<(e + 255) / 256, 256, 0, sA>>>(src, dst, e);
    cudaEventRecord(eA, sA);

    // GEMM1 + buildM on main stream (concurrent with CSR build)
    gemm1_kernel<<<(n + 255) / 256, 256>>>(features, W1, b1, n);
    buildM_kernel<<<(HF * 192 + 255) / 256, 256>>>(W2);

    // Join: SpMM needs both g_x (gemm1) and CSR
    cudaStreamWaitEvent(0, eA, 0);

    int spmm_blocks = (n + 7) / 8;    // 8 warps/block, warp per node
    spmm_kernel<<<spmm_blocks, 256>>>(n, 0);
    spmm_kernel<<<spmm_blocks, 256>>>(n, 1);

    gemm2_kernel<<<(n + 255) / 256, 256>>>(b2, out, n);

    cudaEventDestroy(e0);
    cudaEventDestroy(eA);
    cudaStreamDestroy(sA);
}

// round 6
// speedup vs baseline: 1.1964x; 1.1964x over previous
#include <cuda_runtime.h>

#define N_MAX 50000
#define E_MAX 800000
#define IN_FEATS 128
#define HF 64

// Scratch (device globals; no allocation allowed)
__device__ int   g_cnt[N_MAX];
__device__ int   g_off[N_MAX + 1];
__device__ int   g_cur[N_MAX];
__device__ int   g_bsum[256];
__device__ int   g_esrc[E_MAX];
__device__ float g_dinv[N_MAX];
__device__ float g_x[N_MAX * HF];
__device__ float g_f1[N_MAX * HF];
__device__ float g_f2[N_MAX * HF];
__device__ float g_M[HF * 192];

// ---------------------------------------------------------------------------
__global__ void zero_cnt_kernel(int n) {
    int i = blockIdx.x * blockDim.x + threadIdx.x;
    if (i < n) g_cnt[i] = 0;
}

__global__ void count_kernel(const int* __restrict__ dst, int e) {
    int i = blockIdx.x * blockDim.x + threadIdx.x;
    if (i < e) atomicAdd(&g_cnt[dst[i]], 1);
}

// ---- prefix scan over g_cnt -> g_off (exclusive) ----------------------------
__global__ void scan1_kernel(int n) {
    __shared__ int sh[256];
    int t = threadIdx.x;
    int i = blockIdx.x * 256 + t;
    int v = (i < n) ? g_cnt[i] : 0;
    sh[t] = v;
    __syncthreads();
#pragma unroll
    for (int o = 1; o < 256; o <<= 1) {
        int add = (t >= o) ? sh[t - o] : 0;
        __syncthreads();
        sh[t] += add;
        __syncthreads();
    }
    if (i < n) g_off[i] = sh[t] - v;
    if (t == 255) g_bsum[blockIdx.x] = sh[255];
}

__global__ void scan2_kernel(int nb) {
    __shared__ int sh[256];
    int t = threadIdx.x;
    int v = (t < nb) ? g_bsum[t] : 0;
    sh[t] = v;
    __syncthreads();
#pragma unroll
    for (int o = 1; o < 256; o <<= 1) {
        int add = (t >= o) ? sh[t - o] : 0;
        __syncthreads();
        sh[t] += add;
        __syncthreads();
    }
    if (t < nb) g_bsum[t] = sh[t] - v;
}

// scan3 + dinv fused
__global__ void scan3_kernel(int n, int e) {
    int i = blockIdx.x * blockDim.x + threadIdx.x;
    if (i < n) {
        int o = g_off[i] + g_bsum[i >> 8];
        g_off[i] = o;
        g_cur[i] = o;
        g_dinv[i] = rsqrtf(fmaxf((float)g_cnt[i], 1.0f));
    }
    if (i == 0) g_off[n] = e;
}

__global__ void fill_kernel(const int* __restrict__ src,
                            const int* __restrict__ dst, int e) {
    int i = blockIdx.x * blockDim.x + threadIdx.x;
    if (i < e) {
        int d = dst[i];
        int pos = atomicAdd(&g_cur[d], 1);
        g_esrc[pos] = src[i];
    }
}

// ---------------------------------------------------------------------------
// Gather SpMM: fout[d] = fin[d] - dinv[d] * sum_{s in N(d)} dinv[s]*fin[s]
// One warp per dst node. 16 lanes per edge (float4 = 64 floats / 16 lanes),
// TWO edges in flight per warp (pair = lane>>4), next-index prefetch,
// cross-pair reduction via shfl_xor(16).
// step 0: g_x -> g_f1;  step 1: g_f1 -> g_f2.
__global__ __launch_bounds__(256) void spmm_kernel(int n, int step) {
    const float* fin = (step == 0) ? g_x : g_f1;
    float* fout      = (step == 0) ? g_f1 : g_f2;
    int w = (blockIdx.x * blockDim.x + threadIdx.x) >> 5;
    int lane = threadIdx.x & 31;
    if (w >= n) return;
    int c = lane & 15;        // float4 column 0..15
    int pair = lane >> 4;     // 0 or 1: which edge of the in-flight pair
    int beg = g_off[w];
    int end = g_off[w + 1];
    const float4* F4 = reinterpret_cast<const float4*>(fin);
    float4 acc = make_float4(0.f, 0.f, 0.f, 0.f);

    int j = beg + pair;
    int s_next = (j < end) ? __ldg(&g_esrc[j]) : 0;
    while (j < end) {
        int s = s_next;
        int jn = j + 2;
        if (jn < end) s_next = __ldg(&g_esrc[jn]);
        float wt = __ldg(&g_dinv[s]);
        float4 v = F4[(size_t)s * 16 + c];
        acc.x = fmaf(wt, v.x, acc.x);
        acc.y = fmaf(wt, v.y, acc.y);
        acc.z = fmaf(wt, v.z, acc.z);
        acc.w = fmaf(wt, v.w, acc.w);
        j = jn;
    }

    // Reduce the two pair-halves: lane L and lane L^16 hold partial sums
    // for the same feature chunk c.
    acc.x += __shfl_xor_sync(0xffffffffu, acc.x, 16);
    acc.y += __shfl_xor_sync(0xffffffffu, acc.y, 16);
    acc.z += __shfl_xor_sync(0xffffffffu, acc.z, 16);
    acc.w += __shfl_xor_sync(0xffffffffu, acc.w, 16);

    if (pair == 0) {
        float wd = g_dinv[w];
        float4 xv = F4[(size_t)w * 16 + c];
        float4 r = make_float4(xv.x - wd * acc.x, xv.y - wd * acc.y,
                               xv.z - wd * acc.z, xv.w - wd * acc.w);
        reinterpret_cast<float4*>(fout)[(size_t)w * 16 + c] = r;
    }
}

// ---------------------------------------------------------------------------
// GEMM1: g_x = relu(features[n,128] @ W1[64,128]^T + b1)
// 256 threads, M-tile 128, N=64. Each thread: 4 rows x 8 cols. (R3 config.)
__global__ __launch_bounds__(256) void gemm1_kernel(
    const float* __restrict__ A, const float* __restrict__ W1,
    const float* __restrict__ b1, int n) {
    __shared__ float As[32][132];
    __shared__ float Bs[32][68];
    int t = threadIdx.x;
    int m0 = blockIdx.x * 128;
    int tx = t & 7, ty = t >> 3;       // tx: 8 col-groups, ty: 32 row-groups
    int kv = t & 7, m4 = t >> 3;       // A-load mapping

    float acc[4][8];
#pragma unroll
    for (int i = 0; i < 4; i++)
#pragma unroll
        for (int j = 0; j < 8; j++) acc[i][j] = 0.f;

    for (int k0 = 0; k0 < IN_FEATS; k0 += 32) {
#pragma unroll
        for (int i = 0; i < 4; i++) {
            int m = m4 * 4 + i;
            int gm = m0 + m;
            float4 v = make_float4(0.f, 0.f, 0.f, 0.f);
            if (gm < n)
                v = *reinterpret_cast<const float4*>(A + (size_t)gm * IN_FEATS + k0 + kv * 4);
            As[kv * 4 + 0][m] = v.x;
            As[kv * 4 + 1][m] = v.y;
            As[kv * 4 + 2][m] = v.z;
            As[kv * 4 + 3][m] = v.w;
        }
#pragma unroll
        for (int i = 0; i < 2; i++) {
            int fl = t * 2 + i;
            int nn = fl >> 3, kv2 = fl & 7;
            float4 v = *reinterpret_cast<const float4*>(W1 + (size_t)nn * IN_FEATS + k0 + kv2 * 4);
            Bs[kv2 * 4 + 0][nn] = v.x;
            Bs[kv2 * 4 + 1][nn] = v.y;
            Bs[kv2 * 4 + 2][nn] = v.z;
            Bs[kv2 * 4 + 3][nn] = v.w;
        }
        __syncthreads();
#pragma unroll
        for (int k = 0; k < 32; k++) {
            float4 a = *reinterpret_cast<float4*>(&As[k][ty * 4]);
            float4 bA = *reinterpret_cast<float4*>(&Bs[k][tx * 8]);
            float4 bB = *reinterpret_cast<float4*>(&Bs[k][tx * 8 + 4]);
            float av[4] = {a.x, a.y, a.z, a.w};
            float bv[8] = {bA.x, bA.y, bA.z, bA.w, bB.x, bB.y, bB.z, bB.w};
#pragma unroll
            for (int i = 0; i < 4; i++)
#pragma unroll
                for (int j = 0; j < 8; j++)
                    acc[i][j] = fmaf(av[i], bv[j], acc[i][j]);
        }
        __syncthreads();
    }
#pragma unroll
    for (int i = 0; i < 4; i++) {
        int gm = m0 + ty * 4 + i;
        if (gm < n) {
#pragma unroll
            for (int j = 0; j < 8; j++) {
                float v = acc[i][j] + b1[tx * 8 + j];
                g_x[(size_t)gm * HF + tx * 8 + j] = v > 0.f ? v : 0.f;
            }
        }
    }
}

// ---------------------------------------------------------------------------
// Fold thetas into W2: M[r][p*64+c] = sum_j THETA[j][p] * W2[r][j*64+c]
__global__ void buildM_kernel(const float* __restrict__ W2) {
    int t = blockIdx.x * blockDim.x + threadIdx.x;
    if (t >= HF * 192) return;
    int r = t / 192, k = t % 192;
    int p = k >> 6, c = k & 63;
    const float cA[3] = {3.0f, -3.0f, 0.75f};
    const float cB[3] = {0.0f, 3.0f, -1.5f};
    const float cC[3] = {0.0f, 0.0f, 0.75f};
    g_M[t] = cA[p] * W2[r * 192 + c]
           + cB[p] * W2[r * 192 + 64 + c]
           + cC[p] * W2[r * 192 + 128 + c];
}

// GEMM2: out = [x | f1 | f2] @ M^T + b2   (K=192). (R3 config.)
__global__ __launch_bounds__(256) void gemm2_kernel(
    const float* __restrict__ b2, float* __restrict__ out, int n) {
    __shared__ float As[32][132];
    __shared__ float Bs[32][68];
    int t = threadIdx.x;
    int m0 = blockIdx.x * 128;
    int tx = t & 7, ty = t >> 3;
    int kv = t & 7, m4 = t >> 3;

    float acc[4][8];
#pragma unroll
    for (int i = 0; i < 4; i++)
#pragma unroll
        for (int j = 0; j < 8; j++) acc[i][j] = 0.f;

#pragma unroll
    for (int cch = 0; cch < 6; cch++) {
        const float* S = (cch < 2) ? g_x : (cch < 4) ? g_f1 : g_f2;
        int koff = (cch & 1) * 32;
#pragma unroll
        for (int i = 0; i < 4; i++) {
            int m = m4 * 4 + i;
            int gm = m0 + m;
            float4 v = make_float4(0.f, 0.f, 0.f, 0.f);
            if (gm < n)
                v = *reinterpret_cast<const float4*>(S + (size_t)gm * HF + koff + kv * 4);
            As[kv * 4 + 0][m] = v.x;
            As[kv * 4 + 1][m] = v.y;
            As[kv * 4 + 2][m] = v.z;
            As[kv * 4 + 3][m] = v.w;
        }
#pragma unroll
        for (int i = 0; i < 2; i++) {
            int fl = t * 2 + i;
            int nn = fl >> 3, kv2 = fl & 7;
            float4 v = *reinterpret_cast<const float4*>(g_M + (size_t)nn * 192 + cch * 32 + kv2 * 4);
            Bs[kv2 * 4 + 0][nn] = v.x;
            Bs[kv2 * 4 + 1][nn] = v.y;
            Bs[kv2 * 4 + 2][nn] = v.z;
            Bs[kv2 * 4 + 3][nn] = v.w;
        }
        __syncthreads();
#pragma unroll
        for (int k = 0; k < 32; k++) {
            float4 a = *reinterpret_cast<float4*>(&As[k][ty * 4]);
            float4 bA = *reinterpret_cast<float4*>(&Bs[k][tx * 8]);
            float4 bB = *reinterpret_cast<float4*>(&Bs[k][tx * 8 + 4]);
            float av[4] = {a.x, a.y, a.z, a.w};
            float bv[8] = {bA.x, bA.y, bA.z, bA.w, bB.x, bB.y, bB.z, bB.w};
#pragma unroll
            for (int i = 0; i < 4; i++)
#pragma unroll
                for (int j = 0; j < 8; j++)
                    acc[i][j] = fmaf(av[i], bv[j], acc[i][j]);
        }
        __syncthreads();
    }
#pragma unroll
    for (int i = 0; i < 4; i++) {
        int gm = m0 + ty * 4 + i;
        if (gm < n) {
#pragma unroll
            for (int j = 0; j < 8; j++)
                out[(size_t)gm * HF + tx * 8 + j] = acc[i][j] + b2[tx * 8 + j];
        }
    }
}

// ---------------------------------------------------------------------------
extern "C" void kernel_launch(void* const* d_in, const int* in_sizes, int n_in,
                              void* d_out, int out_size) {
    const float* features = (const float*)d_in[0];
    const int*   src      = (const int*)d_in[1];
    const int*   dst      = (const int*)d_in[2];
    const float* W1       = (const float*)d_in[3];
    const float* b1       = (const float*)d_in[4];
    const float* W2       = (const float*)d_in[5];
    const float* b2       = (const float*)d_in[6];
    float* out = (float*)d_out;

    int n = in_sizes[0] / IN_FEATS;   // 50000
    int e = in_sizes[1];              // 800000
    int nb = (n + 255) / 256;         // 196

    zero_cnt_kernel<<<nb, 256>>>(n);
    count_kernel<<<(e + 255) / 256, 256>>>(dst, e);
    scan1_kernel<<<nb, 256>>>(n);
    scan2_kernel<<<1, 256>>>(nb);
    scan3_kernel<<<nb, 256>>>(n, e);
    fill_kernel<<<(e + 255) / 256, 256>>>(src, dst, e);

    gemm1_kernel<<<(n + 127) / 128, 256>>>(features, W1, b1, n);
    buildM_kernel<<<(HF * 192 + 255) / 256, 256>>>(W2);

    int spmm_blocks = (n + 7) / 8;    // 8 warps/block, warp per node
    spmm_kernel<<<spmm_blocks, 256>>>(n, 0);
    spmm_kernel<<<spmm_blocks, 256>>>(n, 1);

    gemm2_kernel<<<(n + 127) / 128, 256>>>(b2, out, n);
}